// round 15
// baseline (speedup 1.0000x reference)
#include <cuda_runtime.h>
#include <cuda_fp16.h>
#include <math.h>

#define NH 8

typedef unsigned long long u64;
typedef unsigned int u32;

// ---------------- scratch (static __device__, no allocation) ----------------
__device__ float g_qkv[4096 * 24 * 64];          // [v][jh][d], jh: 0-7 q, 8-15 k, 16-23 v
__device__ u32   g_ln[2048 * 8 * 64 * 32];       // [b][h][l][d/2] f16x2 (lo=even d, hi=odd d)
__device__ float g_word[2048 * 2048];            // [b][f]
// const tables (built by k_const each launch)
__device__ u32 g_B2h[2048], g_B2l[2048];         // W_pos interleaved, B-frag split
__device__ u32 g_B3h[2048], g_B3l[2048];         // cos/sin table, B-frag split
__device__ float2 g_rotc[2048];                  // [l][q] (cos(a_q l)/62, sin(a_q l)/62)

__device__ __forceinline__ void fma2(u64& d, u64 a, u64 b) {
    asm("fma.rn.f32x2 %0, %1, %2, %3;" : "=l"(d) : "l"(a), "l"(b), "l"(d));
}
__device__ __forceinline__ u64 pk2(float lo, float hi) {
    u64 r; asm("mov.b64 %0, {%1, %2};" : "=l"(r) : "f"(lo), "f"(hi)); return r;
}
__device__ __forceinline__ float2 up2(u64 v) {
    float2 r; asm("mov.b64 {%0, %1}, %2;" : "=f"(r.x), "=f"(r.y) : "l"(v)); return r;
}

// ---------------- f16 pack/unpack ----------------
__device__ __forceinline__ u32 pkhf(float e, float o) {   // e -> low half, o -> high half
    u32 r; asm("cvt.rn.f16x2.f32 %0, %1, %2;" : "=r"(r) : "f"(o), "f"(e)); return r;
}
__device__ __forceinline__ float2 uphf(u32 w) {
    __half2 h = *reinterpret_cast<__half2*>(&w);
    return __half22float2(h);
}

// ---------------- cp.async helpers ----------------
__device__ __forceinline__ void cp16(void* smem_ptr, const void* gptr) {
    u32 sa = (u32)__cvta_generic_to_shared(smem_ptr);
    asm volatile("cp.async.ca.shared.global [%0], [%1], 16;" :: "r"(sa), "l"(gptr));
}
#define CP_COMMIT() asm volatile("cp.async.commit_group;" ::: "memory")
#define CP_WAIT0()  asm volatile("cp.async.wait_group 0;" ::: "memory")

// ---------------- bf16 split helpers ----------------
__device__ __forceinline__ u32 pkbf(float e, float o) {   // e -> low half, o -> high half
    u32 r; asm("cvt.rn.bf16x2.f32 %0, %1, %2;" : "=r"(r) : "f"(o), "f"(e)); return r;
}
__device__ __forceinline__ float bflo(u32 w) { return __uint_as_float(w << 16); }
__device__ __forceinline__ float bfhi(u32 w) { return __uint_as_float(w & 0xffff0000u); }
__device__ __forceinline__ void split_pair(float e, float o, u32& h, u32& l) {
    h = pkbf(e, o);
    l = pkbf(e - bflo(h), o - bfhi(h));
}

// ---------------- fragment-arranged smem stores (validated R8/R9) ----------------
__device__ __forceinline__ void a_store4(u32* AH, u32* AL, int m, int k0, float4 x) {
    int w = m >> 4, r = m & 15;
    int ks = k0 >> 4, kin = k0 & 15;
    int base = ((w * 4 + ks) * 32 + 4 * (r & 7) + ((kin & 7) >> 1)) * 4 + (r >> 3) + ((kin >> 3) << 1);
    u32 h0, l0, h1, l1;
    split_pair(x.x, x.y, h0, l0);
    split_pair(x.z, x.w, h1, l1);
    AH[base] = h0; AL[base] = l0;
    AH[base + 4] = h1; AL[base + 4] = l1;
}
__device__ __forceinline__ void b_store4n(u32* BH, u32* BL, int n, int k0, float4 x) {
    int ks = k0 >> 4, kin = k0 & 15;
    int base = ((ks * 8 + (n >> 3)) * 32 + 4 * (n & 7) + ((kin & 7) >> 1)) * 2 + (kin >> 3);
    u32 h0, l0, h1, l1;
    split_pair(x.x, x.y, h0, l0);
    split_pair(x.z, x.w, h1, l1);
    BH[base] = h0; BL[base] = l0;
    BH[base + 2] = h1; BL[base + 2] = l1;
}
__device__ __forceinline__ void b_store4k(u32* BH, u32* BL, int k, int n0, float4 ev, float4 od) {
    int ks = k >> 4, kin = k & 15;
    int tig = (kin & 7) >> 1, hi8 = kin >> 3;
    float e[4] = {ev.x, ev.y, ev.z, ev.w};
    float o[4] = {od.x, od.y, od.z, od.w};
#pragma unroll
    for (int j = 0; j < 4; j++) {
        int n = n0 + j;
        int base = ((ks * 8 + (n >> 3)) * 32 + 4 * (n & 7) + tig) * 2 + hi8;
        u32 h, l;
        split_pair(e[j], o[j], h, l);
        BH[base] = h; BL[base] = l;
    }
}

__device__ __forceinline__ void mma_bf16(float* c, const u32* a, const u32* b) {
    asm volatile("mma.sync.aligned.m16n8k16.row.col.f32.bf16.bf16.f32 "
                 "{%0,%1,%2,%3}, {%4,%5,%6,%7}, {%8,%9}, {%0,%1,%2,%3};"
                 : "+f"(c[0]), "+f"(c[1]), "+f"(c[2]), "+f"(c[3])
                 : "r"(a[0]), "r"(a[1]), "r"(a[2]), "r"(a[3]), "r"(b[0]), "r"(b[1]));
}

// full 64x64x64 GEMM from smem operands (validated R8)
#define MMA_GEMM(c, AH, AL, BH, BL, w, lane)                               \
    _Pragma("unroll") for (int ks_ = 0; ks_ < 4; ks_++) {                  \
        uint4 ah_ = *(const uint4*)&AH[(((w) * 4 + ks_) * 32 + (lane)) * 4]; \
        uint4 al_ = *(const uint4*)&AL[(((w) * 4 + ks_) * 32 + (lane)) * 4]; \
        _Pragma("unroll") for (int nt_ = 0; nt_ < 8; nt_++) {              \
            uint2 bh_ = *(const uint2*)&BH[((ks_ * 8 + nt_) * 32 + (lane)) * 2]; \
            uint2 bl_ = *(const uint2*)&BL[((ks_ * 8 + nt_) * 32 + (lane)) * 2]; \
            mma_bf16(c[nt_], (const u32*)&ah_, (const u32*)&bh_);          \
            mma_bf16(c[nt_], (const u32*)&ah_, (const u32*)&bl_);          \
            mma_bf16(c[nt_], (const u32*)&al_, (const u32*)&bh_);          \
        }                                                                  \
    }

// in-register C-fragment (tiles nt0, nt1) -> split A-fragment for k-chunk
__device__ __forceinline__ void c2a(const float* c0, const float* c1, u32* ah, u32* al) {
    ah[0] = pkbf(c0[0], c0[1]); al[0] = pkbf(c0[0] - bflo(ah[0]), c0[1] - bfhi(ah[0]));
    ah[1] = pkbf(c0[2], c0[3]); al[1] = pkbf(c0[2] - bflo(ah[1]), c0[3] - bfhi(ah[1]));
    ah[2] = pkbf(c1[0], c1[1]); al[2] = pkbf(c1[0] - bflo(ah[2]), c1[1] - bfhi(ah[2]));
    ah[3] = pkbf(c1[2], c1[3]); al[3] = pkbf(c1[2] - bflo(ah[3]), c1[3] - bfhi(ah[3]));
}

// ---------------- K0a: qkv table = W_emb @ W_qkv^T (unchanged, validated) ----------------
__global__ __launch_bounds__(128) void k_qkv(const float* __restrict__ W_emb,
                                             const float* __restrict__ W_qkv) {
    __shared__ u32 AH[2048], AL[2048], BH[2048], BL[2048];
    int v0 = blockIdx.y * 64, r0 = blockIdx.x * 64, t = threadIdx.x;
    for (int i = t; i < 1024; i += 128) {
        int row = i >> 4, k0 = (i & 15) * 4;
        a_store4(AH, AL, row, k0, *(const float4*)&W_emb[(size_t)(v0 + row) * 64 + k0]);
        b_store4n(BH, BL, row, k0, *(const float4*)&W_qkv[(size_t)(r0 + row) * 64 + k0]);
    }
    __syncthreads();
    int lane = t & 31, w = t >> 5, grp = lane >> 2, tig = lane & 3;
    float c[8][4] = {};
    MMA_GEMM(c, AH, AL, BH, BL, w, lane);
    int row = v0 + 16 * w + grp;
#pragma unroll
    for (int nt = 0; nt < 8; nt++) {
        int col = r0 + 8 * nt + 2 * tig;
        *(float2*)&g_qkv[(size_t)row * 1536 + col] = make_float2(c[nt][0], c[nt][1]);
        *(float2*)&g_qkv[(size_t)(row + 8) * 1536 + col] = make_float2(c[nt][2], c[nt][3]);
    }
}

// ---------------- K0b: const tables (unchanged, validated) ----------------
__global__ __launch_bounds__(256) void k_const(const float* __restrict__ W_pos) {
    int i = blockIdx.x * 256 + threadIdx.x;
    const float W0 = 6.283185307179586f / 63.0f;
    if (i < 1024) {
        int n = i >> 4, k0 = (i & 15) * 4;
        int q = n >> 1, p = (n & 1) ? q + 31 : q;
        float4 v = make_float4(0.f, 0.f, 0.f, 0.f);
        if (q < 31) v = *(const float4*)&W_pos[p * 64 + k0];
        b_store4n(g_B2h, g_B2l, n, k0, v);
    } else if (i < 2048) {
        int ii = i - 1024;
        int m = ii >> 4, r4 = ii & 15;
        int q0 = 2 * r4, q1 = 2 * r4 + 1;
        float4 v;
        float s, c;
        if (q0 < 31) { sincosf((float)(q0 + 1) * (float)m * W0, &s, &c); v.x = c; v.y = s; }
        else { v.x = 0.f; v.y = 0.f; }
        if (q1 < 31) { sincosf((float)(q1 + 1) * (float)m * W0, &s, &c); v.z = c; v.w = s; }
        else { v.z = 0.f; v.w = 0.f; }
        b_store4n(g_B3h, g_B3l, m, 4 * r4, v);
    } else if (i < 4096) {
        int ii = i - 2048;
        int l = ii >> 5, q = ii & 31;
        float2 r = make_float2(0.f, 0.f);
        if (q < 31) {
            float s, c;
            sincosf((float)(q + 1) * (float)l * W0, &s, &c);
            r = make_float2(c * (1.0f / 62.0f), s * (1.0f / 62.0f));
        }
        g_rotc[ii] = r;
    }
}

// ---------------- K1: fused attention; V reuses Q smem; f16 ln output ----------------
__global__ __launch_bounds__(128) void k_attn(const int* __restrict__ inputs,
                                              const float* __restrict__ ln_g,
                                              const float* __restrict__ ln_b) {
    __shared__ u32 QAH[2048], QAL[2048], KBH[2048], KBL[2048];
    int h = blockIdx.x, b = blockIdx.y, t = threadIdx.x;
    for (int i = t; i < 1024; i += 128) {
        int row = i >> 4, k0 = (i & 15) * 4;
        int tok = inputs[b * 64 + row];
        size_t base = (size_t)tok * 1536 + h * 64 + k0;
        a_store4(QAH, QAL, row, k0, *(const float4*)&g_qkv[base]);
        b_store4n(KBH, KBL, row, k0, *(const float4*)&g_qkv[base + 512]);
    }
    __syncthreads();
    int lane = t & 31, w = t >> 5, grp = lane >> 2, tig = lane & 3;
    int l1 = 16 * w + grp, l2 = l1 + 8;

    // GEMM1: sim = Q @ K^T
    float cs[8][4] = {};
    MMA_GEMM(cs, QAH, QAL, KBH, KBL, w, lane);
    __syncthreads();   // all warps done reading QA -> reuse it for V

    // fill V into the (now free) QA buffers, as B-frag k-major
    for (int i = t; i < 512; i += 128) {
        int kp = i >> 4, d0 = (i & 15) * 4;
        int te = inputs[b * 64 + 2 * kp], to = inputs[b * 64 + 2 * kp + 1];
        float4 ev = *(const float4*)&g_qkv[(size_t)te * 1536 + 1024 + h * 64 + d0];
        float4 od = *(const float4*)&g_qkv[(size_t)to * 1536 + 1024 + h * 64 + d0];
        b_store4k(QAH, QAL, 2 * kp, d0, ev, od);
    }

    // scale, mask (z init in cs), clip (sc)
    float sc[8][4];
#pragma unroll
    for (int nt = 0; nt < 8; nt++) {
        int col = 8 * nt + 2 * tig;
        int m0 = (inputs[b * 64 + col] == 0);
        int m1 = (inputs[b * 64 + col + 1] == 0);
#pragma unroll
        for (int v = 0; v < 4; v++) {
            float s = cs[nt][v] * 0.125f;
            int mv = (v & 1) ? m1 : m0;
            sc[nt][v] = mv ? 0.f : s;
            cs[nt][v] = mv ? -1e9f : s;
        }
    }

    // GEMM2: posw = sclip @ B2
    float cpw[8][4] = {};
#pragma unroll
    for (int ks = 0; ks < 4; ks++) {
        u32 ah[4], al[4];
        c2a(sc[2 * ks], sc[2 * ks + 1], ah, al);
#pragma unroll
        for (int nt = 0; nt < 8; nt++) {
            int bi = ((ks * 8 + nt) * 32 + lane) * 2;
            uint2 bh = *(const uint2*)&g_B2h[bi];
            uint2 bl = *(const uint2*)&g_B2l[bi];
            mma_bf16(cpw[nt], ah, (const u32*)&bh);
            mma_bf16(cpw[nt], ah, (const u32*)&bl);
            mma_bf16(cpw[nt], al, (const u32*)&bh);
        }
    }

    // rotate
#pragma unroll
    for (int nt = 0; nt < 8; nt++) {
        int q = 4 * nt + tig;
        float2 r1 = g_rotc[l1 * 32 + q];
        float2 r2 = g_rotc[l2 * 32 + q];
        float u0 = cpw[nt][0], u1 = cpw[nt][1];
        cpw[nt][0] = u0 * r1.x - u1 * r1.y;
        cpw[nt][1] = u0 * r1.y + u1 * r1.x;
        u0 = cpw[nt][2]; u1 = cpw[nt][3];
        cpw[nt][2] = u0 * r2.x - u1 * r2.y;
        cpw[nt][3] = u0 * r2.y + u1 * r2.x;
    }

    // GEMM3: z = sim_masked + rotated @ B3
#pragma unroll
    for (int ks = 0; ks < 4; ks++) {
        u32 ah[4], al[4];
        c2a(cpw[2 * ks], cpw[2 * ks + 1], ah, al);
#pragma unroll
        for (int nt = 0; nt < 8; nt++) {
            int bi = ((ks * 8 + nt) * 32 + lane) * 2;
            uint2 bh = *(const uint2*)&g_B3h[bi];
            uint2 bl = *(const uint2*)&g_B3l[bi];
            mma_bf16(cs[nt], ah, (const u32*)&bh);
            mma_bf16(cs[nt], ah, (const u32*)&bl);
            mma_bf16(cs[nt], al, (const u32*)&bh);
        }
    }

    // softmax
#pragma unroll
    for (int s = 0; s < 2; s++) {
        float mx = -3.4e38f;
#pragma unroll
        for (int nt = 0; nt < 8; nt++)
            mx = fmaxf(mx, fmaxf(cs[nt][2 * s], cs[nt][2 * s + 1]));
        mx = fmaxf(mx, __shfl_xor_sync(0xffffffffu, mx, 1));
        mx = fmaxf(mx, __shfl_xor_sync(0xffffffffu, mx, 2));
        float sm = 0.f;
#pragma unroll
        for (int nt = 0; nt < 8; nt++) {
            cs[nt][2 * s] = __expf(cs[nt][2 * s] - mx);
            cs[nt][2 * s + 1] = __expf(cs[nt][2 * s + 1] - mx);
            sm += cs[nt][2 * s] + cs[nt][2 * s + 1];
        }
        sm += __shfl_xor_sync(0xffffffffu, sm, 1);
        sm += __shfl_xor_sync(0xffffffffu, sm, 2);
        float inv = 1.0f / sm;
#pragma unroll
        for (int nt = 0; nt < 8; nt++) {
            cs[nt][2 * s] *= inv;
            cs[nt][2 * s + 1] *= inv;
        }
    }

    __syncthreads();   // V fill complete before GEMM4 reads it

    // GEMM4: out = attn @ V (V lives in QAH/QAL)
    float cav[8][4] = {};
#pragma unroll
    for (int ks = 0; ks < 4; ks++) {
        u32 ah[4], al[4];
        c2a(cs[2 * ks], cs[2 * ks + 1], ah, al);
#pragma unroll
        for (int nt = 0; nt < 8; nt++) {
            uint2 bh = *(const uint2*)&QAH[((ks * 8 + nt) * 32 + lane) * 2];
            uint2 bl = *(const uint2*)&QAL[((ks * 8 + nt) * 32 + lane) * 2];
            mma_bf16(cav[nt], ah, (const u32*)&bh);
            mma_bf16(cav[nt], ah, (const u32*)&bl);
            mma_bf16(cav[nt], al, (const u32*)&bh);
        }
    }

    // layernorm epilogue -> f16x2 packed g_ln
    size_t lo = (size_t)(b * NH + h) * 2048;   // u32 units
#pragma unroll
    for (int s = 0; s < 2; s++) {
        float a[8][2];
#pragma unroll
        for (int nt = 0; nt < 8; nt++) { a[nt][0] = cav[nt][2 * s]; a[nt][1] = cav[nt][2 * s + 1]; }
        float sm = 0.f, sq = 0.f;
#pragma unroll
        for (int nt = 0; nt < 8; nt++) {
            sm += a[nt][0] + a[nt][1];
            sq += a[nt][0] * a[nt][0] + a[nt][1] * a[nt][1];
        }
#pragma unroll
        for (int d = 1; d < 4; d <<= 1) {
            sm += __shfl_xor_sync(0xffffffffu, sm, d);
            sq += __shfl_xor_sync(0xffffffffu, sq, d);
        }
        float mu = sm * (1.0f / 64.0f);
        float var = sq * (1.0f / 64.0f) - mu * mu;
        float inv = rsqrtf(var + 1e-5f);
        size_t rb = lo + (size_t)(l1 + 8 * s) * 32;
#pragma unroll
        for (int nt = 0; nt < 8; nt++) {
            int col = 8 * nt + 2 * tig;
            float vx = (a[nt][0] - mu) * inv * ln_g[col] + ln_b[col];
            float vy = (a[nt][1] - mu) * inv * ln_g[col + 1] + ln_b[col + 1];
            g_ln[rb + (col >> 1)] = pkhf(vx, vy);
        }
    }
}

// ---------------- K4: MLP, o-split + cp.async double-buffered f16 ft ----------------
// dyn smem layout (bytes):
//   [0)      W1p  u64[8][32]       2048
//   [2048)   b1p  u64[32]           256
//   [2304)   W2p2 u64[64][16]      8192
//   [10496)  fts  u32[2][8][8][32]16384
//   [26880)  part f32[4][64][33]  33792
//   [60672)  b2s  f32[32]           128
//   [60800)  mskf f32[64]           256   -> total 61056
#define MLP_SMEM 61056
__global__ __launch_bounds__(256, 2) void k_mlp(const int* __restrict__ inputs,
                                                const float* __restrict__ W1,
                                                const float* __restrict__ b1,
                                                const float* __restrict__ W2,
                                                const float* __restrict__ b2) {
    extern __shared__ unsigned char dynsm[];
    u64*   W1p  = (u64*)dynsm;                     // [8][32]
    u64*   b1p  = (u64*)(dynsm + 2048);            // [32]
    u64*   W2p2 = (u64*)(dynsm + 2304);            // [64][16]
    u32*   fts  = (u32*)(dynsm + 10496);           // [2][8][8][32]
    float* part = (float*)(dynsm + 26880);         // [4][64][33]
    float* b2s  = (float*)(dynsm + 60672);
    float* mskf = (float*)(dynsm + 60800);

    int b = blockIdx.x, t = threadIdx.x;
    int d = t & 63, og = t >> 6;
    int dw = d >> 1, dodd = d & 1;
    if (t < 64) mskf[t] = (inputs[b * 64 + t] != 0) ? 1.f : 0.f;
    if (t < 32) { b2s[t] = b2[t]; b1p[t] = pk2(b1[2 * t], b1[2 * t + 1]); }
    {
        int op = t & 31, hh = t >> 5;
        if (t < 256) W1p[hh * 32 + op] = pk2(W1[(2 * op) * 8 + hh], W1[(2 * op + 1) * 8 + hh]);
    }
    for (int i = t; i < 1024; i += 256) {
        int o = i >> 4, q = i & 15;
        W2p2[o * 16 + q] = pk2(W2[(2 * q) * 64 + o], W2[(2 * q + 1) * 64 + o]);
    }

    // prologue: async-fill chunk 0 (512 cp16 = 8KB)
    for (int i = t; i < 512; i += 256) {
        int ll = i >> 6, hh = (i >> 3) & 7, dv = i & 7;
        cp16(&fts[(ll * 8 + hh) * 32 + dv * 4],
             &g_ln[(((size_t)b * 8 + hh) * 64 + ll) * 32 + dv * 4]);
    }
    CP_COMMIT();
    __syncthreads();
    float cnt = 0.f;
#pragma unroll
    for (int m = 0; m < 64; m++) cnt += mskf[m];

    u64 binit[8];
#pragma unroll
    for (int pi = 0; pi < 8; pi++) binit[pi] = b1p[og * 8 + pi];
    float hs[16];
#pragma unroll
    for (int o2 = 0; o2 < 16; o2++) hs[o2] = 0.f;

#pragma unroll 1
    for (int lc = 0; lc < 8; lc++) {
        CP_WAIT0();
        __syncthreads();
        if (lc + 1 < 8) {
            int nb = (lc + 1) & 1;
            for (int i = t; i < 512; i += 256) {
                int ll = i >> 6, hh = (i >> 3) & 7, dv = i & 7;
                cp16(&fts[nb * 2048 + (ll * 8 + hh) * 32 + dv * 4],
                     &g_ln[(((size_t)b * 8 + hh) * 64 + (lc + 1) * 8 + ll) * 32 + dv * 4]);
            }
            CP_COMMIT();
        }
        const u32* fb = fts + (lc & 1) * 2048;
#pragma unroll
        for (int lp = 0; lp < 4; lp++) {
            int l0 = lc * 8 + 2 * lp;
            float m0 = mskf[l0], m1 = mskf[l0 + 1];
            if (m0 + m1 == 0.f) continue;
            u64 va[8], vb[8];
#pragma unroll
            for (int pi = 0; pi < 8; pi++) { va[pi] = binit[pi]; vb[pi] = binit[pi]; }
#pragma unroll
            for (int hh = 0; hh < 8; hh++) {
                u32 w0 = fb[((2 * lp) * 8 + hh) * 32 + dw];
                u32 w1 = fb[((2 * lp + 1) * 8 + hh) * 32 + dw];
                float2 fa = uphf(w0), fc = uphf(w1);
                float a = dodd ? fa.y : fa.x;
                float c = dodd ? fc.y : fc.x;
                u64 f0 = pk2(a, a), f1 = pk2(c, c);
                const u64* wrow = &W1p[hh * 32 + og * 8];
                ulonglong2 w01 = *(const ulonglong2*)&wrow[0];
                ulonglong2 w23 = *(const ulonglong2*)&wrow[2];
                ulonglong2 w45 = *(const ulonglong2*)&wrow[4];
                ulonglong2 w67 = *(const ulonglong2*)&wrow[6];
                fma2(va[0], f0, w01.x); fma2(vb[0], f1, w01.x);
                fma2(va[1], f0, w01.y); fma2(vb[1], f1, w01.y);
                fma2(va[2], f0, w23.x); fma2(vb[2], f1, w23.x);
                fma2(va[3], f0, w23.y); fma2(vb[3], f1, w23.y);
                fma2(va[4], f0, w45.x); fma2(vb[4], f1, w45.x);
                fma2(va[5], f0, w45.y); fma2(vb[5], f1, w45.y);
                fma2(va[6], f0, w67.x); fma2(vb[6], f1, w67.x);
                fma2(va[7], f0, w67.y); fma2(vb[7], f1, w67.y);
            }
#pragma unroll
            for (int pi = 0; pi < 8; pi++) {
                float2 A = up2(va[pi]), Bv = up2(vb[pi]);
                hs[2 * pi]     += m0 * fmaxf(A.x, 0.f) + m1 * fmaxf(Bv.x, 0.f);
                hs[2 * pi + 1] += m0 * fmaxf(A.y, 0.f) + m1 * fmaxf(Bv.y, 0.f);
            }
        }
        __syncthreads();
    }

    // fold the thread's 16 o's through W2 into 32 p partials
    u64 acc2[16];
#pragma unroll
    for (int q = 0; q < 16; q++) acc2[q] = 0ull;
#pragma unroll
    for (int o2 = 0; o2 < 16; o2++) {
        int o = og * 16 + o2;
        u64 hv2 = pk2(hs[o2], hs[o2]);
        const u64* w2row = &W2p2[o * 16];
#pragma unroll
        for (int qj = 0; qj < 8; qj++) {
            ulonglong2 w = *(const ulonglong2*)&w2row[2 * qj];
            fma2(acc2[2 * qj], hv2, w.x);
            fma2(acc2[2 * qj + 1], hv2, w.y);
        }
    }
#pragma unroll
    for (int q = 0; q < 16; q++) {
        float2 v = up2(acc2[q]);
        part[(og * 64 + d) * 33 + 2 * q] = v.x;
        part[(og * 64 + d) * 33 + 2 * q + 1] = v.y;
    }
    __syncthreads();
    float invc = 1.0f / cnt;
    for (int f = t; f < 2048; f += 256) {
        int dd = f >> 5, p = f & 31;
        float wv = part[dd * 33 + p] + part[(64 + dd) * 33 + p]
                 + part[(128 + dd) * 33 + p] + part[(192 + dd) * 33 + p];
        g_word[(size_t)b * 2048 + f] = wv * invc + b2s[p];
    }
}

// ---------------- K5: name mean over n_words ----------------
__global__ __launch_bounds__(256) void k_name(float* __restrict__ out, int n_words, int total) {
    int idx = blockIdx.x * 256 + threadIdx.x;
    if (idx >= total) return;
    int g = idx >> 11, f = idx & 2047;
    float s = 0.f;
    for (int w = 0; w < n_words; w++)
        s += g_word[(size_t)(g * n_words + w) * 2048 + f];
    out[idx] = s / (float)n_words;
}

// ---------------- launch ----------------
extern "C" void kernel_launch(void* const* d_in, const int* in_sizes, int n_in,
                              void* d_out, int out_size) {
    const int* inputs  = (const int*)d_in[0];
    const float* W_emb = (const float*)d_in[1];
    const float* W_qkv = (const float*)d_in[2];
    const float* W_pos = (const float*)d_in[3];
    const float* ln_g  = (const float*)d_in[4];
    const float* ln_b  = (const float*)d_in[5];
    const float* W1    = (const float*)d_in[6];
    const float* b1    = (const float*)d_in[7];
    const float* W2    = (const float*)d_in[8];
    const float* b2    = (const float*)d_in[9];

    int B = in_sizes[0] / 64;                         // 2048
    int V = in_sizes[1] / 64;                         // 4096
    int n_words = (int)(((long long)B * 2048) / out_size);

    static int mlp_cfg = 0;
    if (!mlp_cfg) {
        cudaFuncSetAttribute(k_mlp, cudaFuncAttributeMaxDynamicSharedMemorySize, MLP_SMEM);
        mlp_cfg = 1;
    }

    k_qkv<<<dim3(24, V / 64), 128>>>(W_emb, W_qkv);
    k_const<<<16, 256>>>(W_pos);
    k_attn<<<dim3(NH, B), 128>>>(inputs, ln_g, ln_b);
    k_mlp<<<B, 256, MLP_SMEM>>>(inputs, W1, b1, W2, b2);
    k_name<<<(out_size + 255) / 256, 256>>>((float*)d_out, n_words, out_size);
}

// round 16
// speedup vs baseline: 1.0176x; 1.0176x over previous
#include <cuda_runtime.h>
#include <math.h>

#define NH 8

typedef unsigned long long u64;
typedef unsigned int u32;

// ---------------- scratch (static __device__, no allocation) ----------------
__device__ float g_qkv[4096 * 24 * 64];          // [v][jh][d], jh: 0-7 q, 8-15 k, 16-23 v
__device__ float g_ln[2048 * 8 * 64 * 64];       // [b][h][l][d]
__device__ float g_word[2048 * 2048];            // [b][f]
// const tables (built by k_const each launch)
__device__ u32 g_B2h[2048], g_B2l[2048];         // W_pos interleaved, B-frag split
__device__ u32 g_B3h[2048], g_B3l[2048];         // cos/sin table, B-frag split
__device__ float2 g_rotc[2048];                  // [l][q] (cos(a_q l)/62, sin(a_q l)/62)

__device__ __forceinline__ void fma2(u64& d, u64 a, u64 b) {
    asm("fma.rn.f32x2 %0, %1, %2, %3;" : "=l"(d) : "l"(a), "l"(b), "l"(d));
}
__device__ __forceinline__ u64 pk2(float lo, float hi) {
    u64 r; asm("mov.b64 %0, {%1, %2};" : "=l"(r) : "f"(lo), "f"(hi)); return r;
}
__device__ __forceinline__ float2 up2(u64 v) {
    float2 r; asm("mov.b64 {%0, %1}, %2;" : "=f"(r.x), "=f"(r.y) : "l"(v)); return r;
}

// ---------------- cp.async helpers ----------------
__device__ __forceinline__ void cp16(void* smem_ptr, const void* gptr) {
    u32 sa = (u32)__cvta_generic_to_shared(smem_ptr);
    asm volatile("cp.async.ca.shared.global [%0], [%1], 16;" :: "r"(sa), "l"(gptr));
}
#define CP_COMMIT() asm volatile("cp.async.commit_group;" ::: "memory")
#define CP_WAIT0()  asm volatile("cp.async.wait_group 0;" ::: "memory")

// ---------------- bf16 split helpers ----------------
__device__ __forceinline__ u32 pkbf(float e, float o) {   // e -> low half, o -> high half
    u32 r; asm("cvt.rn.bf16x2.f32 %0, %1, %2;" : "=r"(r) : "f"(o), "f"(e)); return r;
}
__device__ __forceinline__ float bflo(u32 w) { return __uint_as_float(w << 16); }
__device__ __forceinline__ float bfhi(u32 w) { return __uint_as_float(w & 0xffff0000u); }
__device__ __forceinline__ void split_pair(float e, float o, u32& h, u32& l) {
    h = pkbf(e, o);
    l = pkbf(e - bflo(h), o - bfhi(h));
}

// ---------------- fragment-arranged smem stores (validated R8/R9) ----------------
__device__ __forceinline__ void a_store4(u32* AH, u32* AL, int m, int k0, float4 x) {
    int w = m >> 4, r = m & 15;
    int ks = k0 >> 4, kin = k0 & 15;
    int base = ((w * 4 + ks) * 32 + 4 * (r & 7) + ((kin & 7) >> 1)) * 4 + (r >> 3) + ((kin >> 3) << 1);
    u32 h0, l0, h1, l1;
    split_pair(x.x, x.y, h0, l0);
    split_pair(x.z, x.w, h1, l1);
    AH[base] = h0; AL[base] = l0;
    AH[base + 4] = h1; AL[base + 4] = l1;
}
__device__ __forceinline__ void b_store4n(u32* BH, u32* BL, int n, int k0, float4 x) {
    int ks = k0 >> 4, kin = k0 & 15;
    int base = ((ks * 8 + (n >> 3)) * 32 + 4 * (n & 7) + ((kin & 7) >> 1)) * 2 + (kin >> 3);
    u32 h0, l0, h1, l1;
    split_pair(x.x, x.y, h0, l0);
    split_pair(x.z, x.w, h1, l1);
    BH[base] = h0; BL[base] = l0;
    BH[base + 2] = h1; BL[base + 2] = l1;
}
__device__ __forceinline__ void b_store4k(u32* BH, u32* BL, int k, int n0, float4 ev, float4 od) {
    int ks = k >> 4, kin = k & 15;
    int tig = (kin & 7) >> 1, hi8 = kin >> 3;
    float e[4] = {ev.x, ev.y, ev.z, ev.w};
    float o[4] = {od.x, od.y, od.z, od.w};
#pragma unroll
    for (int j = 0; j < 4; j++) {
        int n = n0 + j;
        int base = ((ks * 8 + (n >> 3)) * 32 + 4 * (n & 7) + tig) * 2 + hi8;
        u32 h, l;
        split_pair(e[j], o[j], h, l);
        BH[base] = h; BL[base] = l;
    }
}

__device__ __forceinline__ void mma_bf16(float* c, const u32* a, const u32* b) {
    asm volatile("mma.sync.aligned.m16n8k16.row.col.f32.bf16.bf16.f32 "
                 "{%0,%1,%2,%3}, {%4,%5,%6,%7}, {%8,%9}, {%0,%1,%2,%3};"
                 : "+f"(c[0]), "+f"(c[1]), "+f"(c[2]), "+f"(c[3])
                 : "r"(a[0]), "r"(a[1]), "r"(a[2]), "r"(a[3]), "r"(b[0]), "r"(b[1]));
}

// full 64x64x64 GEMM from smem operands (validated R8)
#define MMA_GEMM(c, AH, AL, BH, BL, w, lane)                               \
    _Pragma("unroll") for (int ks_ = 0; ks_ < 4; ks_++) {                  \
        uint4 ah_ = *(const uint4*)&AH[(((w) * 4 + ks_) * 32 + (lane)) * 4]; \
        uint4 al_ = *(const uint4*)&AL[(((w) * 4 + ks_) * 32 + (lane)) * 4]; \
        _Pragma("unroll") for (int nt_ = 0; nt_ < 8; nt_++) {              \
            uint2 bh_ = *(const uint2*)&BH[((ks_ * 8 + nt_) * 32 + (lane)) * 2]; \
            uint2 bl_ = *(const uint2*)&BL[((ks_ * 8 + nt_) * 32 + (lane)) * 2]; \
            mma_bf16(c[nt_], (const u32*)&ah_, (const u32*)&bh_);          \
            mma_bf16(c[nt_], (const u32*)&ah_, (const u32*)&bl_);          \
            mma_bf16(c[nt_], (const u32*)&al_, (const u32*)&bh_);          \
        }                                                                  \
    }

// in-register C-fragment (tiles nt0, nt1) -> split A-fragment for k-chunk
__device__ __forceinline__ void c2a(const float* c0, const float* c1, u32* ah, u32* al) {
    ah[0] = pkbf(c0[0], c0[1]); al[0] = pkbf(c0[0] - bflo(ah[0]), c0[1] - bfhi(ah[0]));
    ah[1] = pkbf(c0[2], c0[3]); al[1] = pkbf(c0[2] - bflo(ah[1]), c0[3] - bfhi(ah[1]));
    ah[2] = pkbf(c1[0], c1[1]); al[2] = pkbf(c1[0] - bflo(ah[2]), c1[1] - bfhi(ah[2]));
    ah[3] = pkbf(c1[2], c1[3]); al[3] = pkbf(c1[2] - bflo(ah[3]), c1[3] - bfhi(ah[3]));
}

// ---------------- K0a: qkv table = W_emb @ W_qkv^T (unchanged, validated) ----------------
__global__ __launch_bounds__(128) void k_qkv(const float* __restrict__ W_emb,
                                             const float* __restrict__ W_qkv) {
    __shared__ u32 AH[2048], AL[2048], BH[2048], BL[2048];
    int v0 = blockIdx.y * 64, r0 = blockIdx.x * 64, t = threadIdx.x;
    for (int i = t; i < 1024; i += 128) {
        int row = i >> 4, k0 = (i & 15) * 4;
        a_store4(AH, AL, row, k0, *(const float4*)&W_emb[(size_t)(v0 + row) * 64 + k0]);
        b_store4n(BH, BL, row, k0, *(const float4*)&W_qkv[(size_t)(r0 + row) * 64 + k0]);
    }
    __syncthreads();
    int lane = t & 31, w = t >> 5, grp = lane >> 2, tig = lane & 3;
    float c[8][4] = {};
    MMA_GEMM(c, AH, AL, BH, BL, w, lane);
    int row = v0 + 16 * w + grp;
#pragma unroll
    for (int nt = 0; nt < 8; nt++) {
        int col = r0 + 8 * nt + 2 * tig;
        *(float2*)&g_qkv[(size_t)row * 1536 + col] = make_float2(c[nt][0], c[nt][1]);
        *(float2*)&g_qkv[(size_t)(row + 8) * 1536 + col] = make_float2(c[nt][2], c[nt][3]);
    }
}

// ---------------- K0b: const tables (unchanged, validated) ----------------
__global__ __launch_bounds__(256) void k_const(const float* __restrict__ W_pos) {
    int i = blockIdx.x * 256 + threadIdx.x;
    const float W0 = 6.283185307179586f / 63.0f;
    if (i < 1024) {
        int n = i >> 4, k0 = (i & 15) * 4;
        int q = n >> 1, p = (n & 1) ? q + 31 : q;
        float4 v = make_float4(0.f, 0.f, 0.f, 0.f);
        if (q < 31) v = *(const float4*)&W_pos[p * 64 + k0];
        b_store4n(g_B2h, g_B2l, n, k0, v);
    } else if (i < 2048) {
        int ii = i - 1024;
        int m = ii >> 4, r4 = ii & 15;
        int q0 = 2 * r4, q1 = 2 * r4 + 1;
        float4 v;
        float s, c;
        if (q0 < 31) { sincosf((float)(q0 + 1) * (float)m * W0, &s, &c); v.x = c; v.y = s; }
        else { v.x = 0.f; v.y = 0.f; }
        if (q1 < 31) { sincosf((float)(q1 + 1) * (float)m * W0, &s, &c); v.z = c; v.w = s; }
        else { v.z = 0.f; v.w = 0.f; }
        b_store4n(g_B3h, g_B3l, m, 4 * r4, v);
    } else if (i < 4096) {
        int ii = i - 2048;
        int l = ii >> 5, q = ii & 31;
        float2 r = make_float2(0.f, 0.f);
        if (q < 31) {
            float s, c;
            sincosf((float)(q + 1) * (float)l * W0, &s, &c);
            r = make_float2(c * (1.0f / 62.0f), s * (1.0f / 62.0f));
        }
        g_rotc[ii] = r;
    }
}

// ---------------- K1: fused attention; V reuses Q smem (32KB total) ----------------
__global__ __launch_bounds__(128) void k_attn(const int* __restrict__ inputs,
                                              const float* __restrict__ ln_g,
                                              const float* __restrict__ ln_b) {
    __shared__ u32 QAH[2048], QAL[2048], KBH[2048], KBL[2048];
    int h = blockIdx.x, b = blockIdx.y, t = threadIdx.x;
    for (int i = t; i < 1024; i += 128) {
        int row = i >> 4, k0 = (i & 15) * 4;
        int tok = inputs[b * 64 + row];
        size_t base = (size_t)tok * 1536 + h * 64 + k0;
        a_store4(QAH, QAL, row, k0, *(const float4*)&g_qkv[base]);
        b_store4n(KBH, KBL, row, k0, *(const float4*)&g_qkv[base + 512]);
    }
    __syncthreads();
    int lane = t & 31, w = t >> 5, grp = lane >> 2, tig = lane & 3;
    int l1 = 16 * w + grp, l2 = l1 + 8;

    // GEMM1: sim = Q @ K^T
    float cs[8][4] = {};
    MMA_GEMM(cs, QAH, QAL, KBH, KBL, w, lane);
    __syncthreads();   // all warps done reading QA -> reuse it for V

    // fill V into the (now free) QA buffers, as B-frag k-major
    for (int i = t; i < 512; i += 128) {
        int kp = i >> 4, d0 = (i & 15) * 4;
        int te = inputs[b * 64 + 2 * kp], to = inputs[b * 64 + 2 * kp + 1];
        float4 ev = *(const float4*)&g_qkv[(size_t)te * 1536 + 1024 + h * 64 + d0];
        float4 od = *(const float4*)&g_qkv[(size_t)to * 1536 + 1024 + h * 64 + d0];
        b_store4k(QAH, QAL, 2 * kp, d0, ev, od);
    }

    // scale, mask (z init in cs), clip (sc)
    float sc[8][4];
#pragma unroll
    for (int nt = 0; nt < 8; nt++) {
        int col = 8 * nt + 2 * tig;
        int m0 = (inputs[b * 64 + col] == 0);
        int m1 = (inputs[b * 64 + col + 1] == 0);
#pragma unroll
        for (int v = 0; v < 4; v++) {
            float s = cs[nt][v] * 0.125f;
            int mv = (v & 1) ? m1 : m0;
            sc[nt][v] = mv ? 0.f : s;
            cs[nt][v] = mv ? -1e9f : s;
        }
    }

    // GEMM2: posw = sclip @ B2
    float cpw[8][4] = {};
#pragma unroll
    for (int ks = 0; ks < 4; ks++) {
        u32 ah[4], al[4];
        c2a(sc[2 * ks], sc[2 * ks + 1], ah, al);
#pragma unroll
        for (int nt = 0; nt < 8; nt++) {
            int bi = ((ks * 8 + nt) * 32 + lane) * 2;
            uint2 bh = *(const uint2*)&g_B2h[bi];
            uint2 bl = *(const uint2*)&g_B2l[bi];
            mma_bf16(cpw[nt], ah, (const u32*)&bh);
            mma_bf16(cpw[nt], ah, (const u32*)&bl);
            mma_bf16(cpw[nt], al, (const u32*)&bh);
        }
    }

    // rotate
#pragma unroll
    for (int nt = 0; nt < 8; nt++) {
        int q = 4 * nt + tig;
        float2 r1 = g_rotc[l1 * 32 + q];
        float2 r2 = g_rotc[l2 * 32 + q];
        float u0 = cpw[nt][0], u1 = cpw[nt][1];
        cpw[nt][0] = u0 * r1.x - u1 * r1.y;
        cpw[nt][1] = u0 * r1.y + u1 * r1.x;
        u0 = cpw[nt][2]; u1 = cpw[nt][3];
        cpw[nt][2] = u0 * r2.x - u1 * r2.y;
        cpw[nt][3] = u0 * r2.y + u1 * r2.x;
    }

    // GEMM3: z = sim_masked + rotated @ B3
#pragma unroll
    for (int ks = 0; ks < 4; ks++) {
        u32 ah[4], al[4];
        c2a(cpw[2 * ks], cpw[2 * ks + 1], ah, al);
#pragma unroll
        for (int nt = 0; nt < 8; nt++) {
            int bi = ((ks * 8 + nt) * 32 + lane) * 2;
            uint2 bh = *(const uint2*)&g_B3h[bi];
            uint2 bl = *(const uint2*)&g_B3l[bi];
            mma_bf16(cs[nt], ah, (const u32*)&bh);
            mma_bf16(cs[nt], ah, (const u32*)&bl);
            mma_bf16(cs[nt], al, (const u32*)&bh);
        }
    }

    // softmax
#pragma unroll
    for (int s = 0; s < 2; s++) {
        float mx = -3.4e38f;
#pragma unroll
        for (int nt = 0; nt < 8; nt++)
            mx = fmaxf(mx, fmaxf(cs[nt][2 * s], cs[nt][2 * s + 1]));
        mx = fmaxf(mx, __shfl_xor_sync(0xffffffffu, mx, 1));
        mx = fmaxf(mx, __shfl_xor_sync(0xffffffffu, mx, 2));
        float sm = 0.f;
#pragma unroll
        for (int nt = 0; nt < 8; nt++) {
            cs[nt][2 * s] = __expf(cs[nt][2 * s] - mx);
            cs[nt][2 * s + 1] = __expf(cs[nt][2 * s + 1] - mx);
            sm += cs[nt][2 * s] + cs[nt][2 * s + 1];
        }
        sm += __shfl_xor_sync(0xffffffffu, sm, 1);
        sm += __shfl_xor_sync(0xffffffffu, sm, 2);
        float inv = 1.0f / sm;
#pragma unroll
        for (int nt = 0; nt < 8; nt++) {
            cs[nt][2 * s] *= inv;
            cs[nt][2 * s + 1] *= inv;
        }
    }

    __syncthreads();   // V fill complete before GEMM4 reads it

    // GEMM4: out = attn @ V (V lives in QAH/QAL)
    float cav[8][4] = {};
#pragma unroll
    for (int ks = 0; ks < 4; ks++) {
        u32 ah[4], al[4];
        c2a(cs[2 * ks], cs[2 * ks + 1], ah, al);
#pragma unroll
        for (int nt = 0; nt < 8; nt++) {
            uint2 bh = *(const uint2*)&QAH[((ks * 8 + nt) * 32 + lane) * 2];
            uint2 bl = *(const uint2*)&QAL[((ks * 8 + nt) * 32 + lane) * 2];
            mma_bf16(cav[nt], ah, (const u32*)&bh);
            mma_bf16(cav[nt], ah, (const u32*)&bl);
            mma_bf16(cav[nt], al, (const u32*)&bh);
        }
    }

    // layernorm epilogue
    size_t lo = (size_t)(b * NH + h) * 4096;
#pragma unroll
    for (int s = 0; s < 2; s++) {
        float a[8][2];
#pragma unroll
        for (int nt = 0; nt < 8; nt++) { a[nt][0] = cav[nt][2 * s]; a[nt][1] = cav[nt][2 * s + 1]; }
        float sm = 0.f, sq = 0.f;
#pragma unroll
        for (int nt = 0; nt < 8; nt++) {
            sm += a[nt][0] + a[nt][1];
            sq += a[nt][0] * a[nt][0] + a[nt][1] * a[nt][1];
        }
#pragma unroll
        for (int d = 1; d < 4; d <<= 1) {
            sm += __shfl_xor_sync(0xffffffffu, sm, d);
            sq += __shfl_xor_sync(0xffffffffu, sq, d);
        }
        float mu = sm * (1.0f / 64.0f);
        float var = sq * (1.0f / 64.0f) - mu * mu;
        float inv = rsqrtf(var + 1e-5f);
        size_t rb = lo + (size_t)(l1 + 8 * s) * 64;
#pragma unroll
        for (int nt = 0; nt < 8; nt++) {
            int col = 8 * nt + 2 * tig;
            float2 v;
            v.x = (a[nt][0] - mu) * inv * ln_g[col] + ln_b[col];
            v.y = (a[nt][1] - mu) * inv * ln_g[col + 1] + ln_b[col + 1];
            *(float2*)&g_ln[rb + col] = v;
        }
    }
}

// ---------------- K4: MLP, o-split + cp.async double-buffered ft ----------------
// dyn smem layout (bytes) — part UNIONS with fts (fts dead at fold time):
//   [0)      W1p  u64[8][32]       2048
//   [2048)   b1p  u64[32]           256
//   [2304)   W2p2 u64[64][16]      8192
//   [10496)  fts  f32[2][8][8][64]32768   (main loop only)
//   [10496)  part f32[4][64][33]  33792   (fold only, overlaps fts)
//   [44288)  b2s  f32[32]           128
//   [44416)  mskf f32[64]           256   -> total 44672
#define MLP_SMEM 44672
__global__ __launch_bounds__(256, 3) void k_mlp(const int* __restrict__ inputs,
                                                const float* __restrict__ W1,
                                                const float* __restrict__ b1,
                                                const float* __restrict__ W2,
                                                const float* __restrict__ b2) {
    extern __shared__ unsigned char dynsm[];
    u64*   W1p  = (u64*)dynsm;                     // [8][32]
    u64*   b1p  = (u64*)(dynsm + 2048);            // [32]
    u64*   W2p2 = (u64*)(dynsm + 2304);            // [64][16]
    float* fts  = (float*)(dynsm + 10496);         // [2][8][8][64]
    float* part = (float*)(dynsm + 10496);         // [4][64][33] (union with fts)
    float* b2s  = (float*)(dynsm + 44288);
    float* mskf = (float*)(dynsm + 44416);

    int b = blockIdx.x, t = threadIdx.x;
    int d = t & 63, og = t >> 6;
    if (t < 64) mskf[t] = (inputs[b * 64 + t] != 0) ? 1.f : 0.f;
    if (t < 32) { b2s[t] = b2[t]; b1p[t] = pk2(b1[2 * t], b1[2 * t + 1]); }
    {
        int op = t & 31, hh = t >> 5;
        if (t < 256) W1p[hh * 32 + op] = pk2(W1[(2 * op) * 8 + hh], W1[(2 * op + 1) * 8 + hh]);
    }
    for (int i = t; i < 1024; i += 256) {
        int o = i >> 4, q = i & 15;
        W2p2[o * 16 + q] = pk2(W2[(2 * q) * 64 + o], W2[(2 * q + 1) * 64 + o]);
    }

    // prologue: async-fill chunk 0
    for (int i = t; i < 1024; i += 256) {
        int ll = i >> 7, hh = (i >> 4) & 7, dv = i & 15;
        cp16(&fts[(ll * 8 + hh) * 64 + dv * 4],
             &g_ln[(((size_t)b * 8 + hh) * 64 + ll) * 64 + dv * 4]);
    }
    CP_COMMIT();
    __syncthreads();
    float cnt = 0.f;
#pragma unroll
    for (int m = 0; m < 64; m++) cnt += mskf[m];

    u64 binit[8];
#pragma unroll
    for (int pi = 0; pi < 8; pi++) binit[pi] = b1p[og * 8 + pi];
    float hs[16];
#pragma unroll
    for (int o2 = 0; o2 < 16; o2++) hs[o2] = 0.f;

#pragma unroll 1
    for (int lc = 0; lc < 8; lc++) {
        CP_WAIT0();
        __syncthreads();   // chunk lc visible; prior compute done
        if (lc + 1 < 8) {  // prefetch next chunk into the other buffer
            int nb = (lc + 1) & 1;
            for (int i = t; i < 1024; i += 256) {
                int ll = i >> 7, hh = (i >> 4) & 7, dv = i & 15;
                cp16(&fts[nb * 4096 + (ll * 8 + hh) * 64 + dv * 4],
                     &g_ln[(((size_t)b * 8 + hh) * 64 + (lc + 1) * 8 + ll) * 64 + dv * 4]);
            }
            CP_COMMIT();
        }
        const float* fb = fts + (lc & 1) * 4096;
#pragma unroll
        for (int lp = 0; lp < 4; lp++) {
            int l0 = lc * 8 + 2 * lp;
            float m0 = mskf[l0], m1 = mskf[l0 + 1];
            if (m0 + m1 == 0.f) continue;
            u64 va[8], vb[8];
#pragma unroll
            for (int pi = 0; pi < 8; pi++) { va[pi] = binit[pi]; vb[pi] = binit[pi]; }
#pragma unroll
            for (int hh = 0; hh < 8; hh++) {
                float a = fb[((2 * lp) * 8 + hh) * 64 + d];
                float c = fb[((2 * lp + 1) * 8 + hh) * 64 + d];
                u64 f0 = pk2(a, a), f1 = pk2(c, c);
                const u64* wrow = &W1p[hh * 32 + og * 8];
                ulonglong2 w01 = *(const ulonglong2*)&wrow[0];
                ulonglong2 w23 = *(const ulonglong2*)&wrow[2];
                ulonglong2 w45 = *(const ulonglong2*)&wrow[4];
                ulonglong2 w67 = *(const ulonglong2*)&wrow[6];
                fma2(va[0], f0, w01.x); fma2(vb[0], f1, w01.x);
                fma2(va[1], f0, w01.y); fma2(vb[1], f1, w01.y);
                fma2(va[2], f0, w23.x); fma2(vb[2], f1, w23.x);
                fma2(va[3], f0, w23.y); fma2(vb[3], f1, w23.y);
                fma2(va[4], f0, w45.x); fma2(vb[4], f1, w45.x);
                fma2(va[5], f0, w45.y); fma2(vb[5], f1, w45.y);
                fma2(va[6], f0, w67.x); fma2(vb[6], f1, w67.x);
                fma2(va[7], f0, w67.y); fma2(vb[7], f1, w67.y);
            }
#pragma unroll
            for (int pi = 0; pi < 8; pi++) {
                float2 A = up2(va[pi]), Bv = up2(vb[pi]);
                hs[2 * pi]     += m0 * fmaxf(A.x, 0.f) + m1 * fmaxf(Bv.x, 0.f);
                hs[2 * pi + 1] += m0 * fmaxf(A.y, 0.f) + m1 * fmaxf(Bv.y, 0.f);
            }
        }
        __syncthreads();   // everyone done with buf[lc&1] before refill / part reuse
    }

    // fold the thread's 16 o's through W2 into 32 p partials (part overlaps dead fts)
    u64 acc2[16];
#pragma unroll
    for (int q = 0; q < 16; q++) acc2[q] = 0ull;
#pragma unroll
    for (int o2 = 0; o2 < 16; o2++) {
        int o = og * 16 + o2;
        u64 hv2 = pk2(hs[o2], hs[o2]);
        const u64* w2row = &W2p2[o * 16];
#pragma unroll
        for (int qj = 0; qj < 8; qj++) {
            ulonglong2 w = *(const ulonglong2*)&w2row[2 * qj];
            fma2(acc2[2 * qj], hv2, w.x);
            fma2(acc2[2 * qj + 1], hv2, w.y);
        }
    }
#pragma unroll
    for (int q = 0; q < 16; q++) {
        float2 v = up2(acc2[q]);
        part[(og * 64 + d) * 33 + 2 * q] = v.x;
        part[(og * 64 + d) * 33 + 2 * q + 1] = v.y;
    }
    __syncthreads();
    float invc = 1.0f / cnt;
    for (int f = t; f < 2048; f += 256) {
        int dd = f >> 5, p = f & 31;
        float wv = part[dd * 33 + p] + part[(64 + dd) * 33 + p]
                 + part[(128 + dd) * 33 + p] + part[(192 + dd) * 33 + p];
        g_word[(size_t)b * 2048 + f] = wv * invc + b2s[p];
    }
}

// ---------------- K5: name mean over n_words ----------------
__global__ __launch_bounds__(256) void k_name(float* __restrict__ out, int n_words, int total) {
    int idx = blockIdx.x * 256 + threadIdx.x;
    if (idx >= total) return;
    int g = idx >> 11, f = idx & 2047;
    float s = 0.f;
    for (int w = 0; w < n_words; w++)
        s += g_word[(size_t)(g * n_words + w) * 2048 + f];
    out[idx] = s / (float)n_words;
}

// ---------------- launch ----------------
extern "C" void kernel_launch(void* const* d_in, const int* in_sizes, int n_in,
                              void* d_out, int out_size) {
    const int* inputs  = (const int*)d_in[0];
    const float* W_emb = (const float*)d_in[1];
    const float* W_qkv = (const float*)d_in[2];
    const float* W_pos = (const float*)d_in[3];
    const float* ln_g  = (const float*)d_in[4];
    const float* ln_b  = (const float*)d_in[5];
    const float* W1    = (const float*)d_in[6];
    const float* b1    = (const float*)d_in[7];
    const float* W2    = (const float*)d_in[8];
    const float* b2    = (const float*)d_in[9];

    int B = in_sizes[0] / 64;                         // 2048
    int V = in_sizes[1] / 64;                         // 4096
    int n_words = (int)(((long long)B * 2048) / out_size);

    static int mlp_cfg = 0;
    if (!mlp_cfg) {
        cudaFuncSetAttribute(k_mlp, cudaFuncAttributeMaxDynamicSharedMemorySize, MLP_SMEM);
        mlp_cfg = 1;
    }

    k_qkv<<<dim3(24, V / 64), 128>>>(W_emb, W_qkv);
    k_const<<<16, 256>>>(W_pos);
    k_attn<<<dim3(NH, B), 128>>>(inputs, ln_g, ln_b);
    k_mlp<<<B, 256, MLP_SMEM>>>(inputs, W1, b1, W2, b2);
    k_name<<<(out_size + 255) / 256, 256>>>((float*)d_out, n_words, out_size);
}